// round 9
// baseline (speedup 1.0000x reference)
#include <cuda_runtime.h>
#include <cstdint>

// Problem constants
#define BB 64
#define NN 1024
#define CC 128
#define DD 64

// Scratch for Q, K, V (relu'd projections), fp32. 48 MB of __device__ globals
// (the sanctioned scratch path; no runtime allocation).
__device__ float g_Q[BB * NN * DD];
__device__ float g_K[BB * NN * DD];
__device__ float g_V[BB * NN * DD];

// Round fp32 -> tf32 (round-to-nearest) and return as a float bit-pattern.
__device__ __forceinline__ float f2tf(float f) {
    uint32_t u;
    asm("cvt.rna.tf32.f32 %0, %1;" : "=r"(u) : "f"(f));
    return __uint_as_float(u);
}

// m16n8k8 tf32 MMA, fp32 accumulate. A row-major, B col-major.
__device__ __forceinline__ void mma_tf32(float* d,
                                         uint32_t a0, uint32_t a1, uint32_t a2, uint32_t a3,
                                         uint32_t b0, uint32_t b1) {
    asm volatile(
        "mma.sync.aligned.m16n8k8.row.col.f32.tf32.tf32.f32 "
        "{%0,%1,%2,%3}, {%4,%5,%6,%7}, {%8,%9}, {%0,%1,%2,%3};"
        : "+f"(d[0]), "+f"(d[1]), "+f"(d[2]), "+f"(d[3])
        : "r"(a0), "r"(a1), "r"(a2), "r"(a3), "r"(b0), "r"(b1));
}

// ============================================================================
// Kernel 1: QKV projection.  q/k/v = relu(x @ W + b)
//   x: [B*N, C] fp32,  W: [C, D] each,  outputs g_Q/g_K/g_V [B*N, D] fp32.
// Tile: 128 rows x 192 cols (Q|K|V concat) per block, K-chunks of 32.
// 256 threads = 8 warps; each warp: 16 rows x 192 cols = 24 n-fragments.
// ============================================================================
__global__ __launch_bounds__(256) void qkv_kernel(
    const float* __restrict__ x,
    const float* __restrict__ Wq, const float* __restrict__ bq,
    const float* __restrict__ Wk, const float* __restrict__ bk,
    const float* __restrict__ Wv, const float* __restrict__ bv)
{
    __shared__ float xs[128 * 36];   // x chunk [128 rows][32 k] stride 36 (banks: 4g+t, conflict-free)
    __shared__ float ws[32 * 200];   // W chunk [32 k][192 n]  stride 200 (banks: 8t+g, conflict-free)

    const int tid  = threadIdx.x;
    const int w    = tid >> 5;
    const int lane = tid & 31;
    const int g    = lane >> 2;   // groupID (row within fragment)
    const int t    = lane & 3;    // threadID in group (col within fragment)
    const int r0   = blockIdx.x * 128;

    float acc[24][4];
#pragma unroll
    for (int i = 0; i < 24; i++)
#pragma unroll
        for (int j = 0; j < 4; j++) acc[i][j] = 0.f;

    for (int kc = 0; kc < 4; kc++) {
        __syncthreads();
        // Load x chunk: 128x32 fp32 = 1024 float4, tf32-converted into smem.
#pragma unroll
        for (int i = 0; i < 4; i++) {
            int v   = tid + i * 256;
            int row = v >> 3;
            int c4  = v & 7;
            float4 xv = *reinterpret_cast<const float4*>(
                x + (size_t)(r0 + row) * CC + kc * 32 + c4 * 4);
            int o = row * 36 + c4 * 4;
            xs[o + 0] = f2tf(xv.x);
            xs[o + 1] = f2tf(xv.y);
            xs[o + 2] = f2tf(xv.z);
            xs[o + 3] = f2tf(xv.w);
        }
        // Load W chunk: 32 x 192 (Wq|Wk|Wv columns).
#pragma unroll
        for (int i = 0; i < 24; i++) {
            int f   = tid + i * 256;
            int row = f / 192;
            int col = f % 192;
            float val;
            if (col < 64)       val = Wq[(kc * 32 + row) * DD + col];
            else if (col < 128) val = Wk[(kc * 32 + row) * DD + col - 64];
            else                val = Wv[(kc * 32 + row) * DD + col - 128];
            ws[row * 200 + col] = f2tf(val);
        }
        __syncthreads();

#pragma unroll
        for (int ksi = 0; ksi < 4; ksi++) {
            int ar = (w * 16 + g) * 36 + ksi * 8 + t;
            uint32_t a0 = __float_as_uint(xs[ar]);
            uint32_t a1 = __float_as_uint(xs[ar + 8 * 36]);
            uint32_t a2 = __float_as_uint(xs[ar + 4]);
            uint32_t a3 = __float_as_uint(xs[ar + 8 * 36 + 4]);
#pragma unroll
            for (int nf = 0; nf < 24; nf++) {
                uint32_t b0 = __float_as_uint(ws[(ksi * 8 + t)     * 200 + nf * 8 + g]);
                uint32_t b1 = __float_as_uint(ws[(ksi * 8 + t + 4) * 200 + nf * 8 + g]);
                mma_tf32(acc[nf], a0, a1, a2, a3, b0, b1);
            }
        }
    }

    // Epilogue: bias + relu, scatter into g_Q/g_K/g_V.
    const int rg = r0 + w * 16 + g;
#pragma unroll
    for (int nf = 0; nf < 24; nf++) {
        int m    = nf >> 3;                 // 0:Q 1:K 2:V
        int dcol = (nf & 7) * 8 + 2 * t;
        const float* bias = (m == 0) ? bq : (m == 1) ? bk : bv;
        float* dst        = (m == 0) ? g_Q : (m == 1) ? g_K : g_V;
        float b0v = bias[dcol], b1v = bias[dcol + 1];
        float2 o0 = make_float2(fmaxf(acc[nf][0] + b0v, 0.f),
                                fmaxf(acc[nf][1] + b1v, 0.f));
        float2 o1 = make_float2(fmaxf(acc[nf][2] + b0v, 0.f),
                                fmaxf(acc[nf][3] + b1v, 0.f));
        *reinterpret_cast<float2*>(dst + (size_t)rg * DD + dcol)       = o0;
        *reinterpret_cast<float2*>(dst + (size_t)(rg + 8) * DD + dcol) = o1;
    }
}

// ============================================================================
// Kernel 2: flash attention + residual.
//   out[b,n,:] = softmax(Q Kt / 8) @ V + Q
// One block per (batch, 64-row q tile). 128 threads = 4 warps, warp w owns
// q rows [w*16, w*16+16). Streams 16 K/V tiles of 64 with online softmax.
// K smem buffer is reused for P after S-phase (dead by then).
// ============================================================================
__global__ __launch_bounds__(128) void attn_kernel(float* __restrict__ out)
{
    __shared__ float ksm[64 * 68];   // K tile (tf32, pre-scaled 1/8); reused as P. banks OK.
    __shared__ float vsm[64 * 72];   // V tile (tf32). stride 72 -> banks 8t+g, conflict-free.

    const int tid  = threadIdx.x;
    const int w    = tid >> 5;
    const int lane = tid & 31;
    const int g    = lane >> 2;
    const int t    = lane & 3;
    const int b    = blockIdx.y;
    const int qt   = blockIdx.x;
    const size_t qrow0 = (size_t)b * NN + qt * 64 + w * 16;

    // Q fragments in registers for all 8 k-steps (D=64). Loaded once, tf32.
    uint32_t qa[8][4];
    {
        const float* qb = g_Q + qrow0 * DD;
#pragma unroll
        for (int ksi = 0; ksi < 8; ksi++) {
            qa[ksi][0] = __float_as_uint(f2tf(qb[(size_t)g * DD + ksi * 8 + t]));
            qa[ksi][1] = __float_as_uint(f2tf(qb[(size_t)(g + 8) * DD + ksi * 8 + t]));
            qa[ksi][2] = __float_as_uint(f2tf(qb[(size_t)g * DD + ksi * 8 + t + 4]));
            qa[ksi][3] = __float_as_uint(f2tf(qb[(size_t)(g + 8) * DD + ksi * 8 + t + 4]));
        }
    }

    float o[8][4];
#pragma unroll
    for (int i = 0; i < 8; i++)
#pragma unroll
        for (int j = 0; j < 4; j++) o[i][j] = 0.f;
    float m0 = -1e30f, m1 = -1e30f;   // running row maxima (rows g, g+8)
    float l0 = 0.f,    l1 = 0.f;      // running row sums

    const int pr0 = (w * 16 + g) * 68;
    const int pr1 = (w * 16 + g + 8) * 68;

    for (int kt = 0; kt < 16; kt++) {
        __syncthreads();   // prior iter's PV reads of ksm(P)/vsm done
        {
            const size_t base = ((size_t)b * NN + kt * 64) * DD;
#pragma unroll
            for (int i = 0; i < 8; i++) {
                int v   = tid + i * 128;
                int row = v >> 4;
                int c4  = v & 15;
                float4 kv = *reinterpret_cast<const float4*>(g_K + base + row * DD + c4 * 4);
                float4 vv = *reinterpret_cast<const float4*>(g_V + base + row * DD + c4 * 4);
                int ko = row * 68 + c4 * 4;
                ksm[ko + 0] = f2tf(kv.x * 0.125f);
                ksm[ko + 1] = f2tf(kv.y * 0.125f);
                ksm[ko + 2] = f2tf(kv.z * 0.125f);
                ksm[ko + 3] = f2tf(kv.w * 0.125f);
                int vo = row * 72 + c4 * 4;
                vsm[vo + 0] = f2tf(vv.x);
                vsm[vo + 1] = f2tf(vv.y);
                vsm[vo + 2] = f2tf(vv.z);
                vsm[vo + 3] = f2tf(vv.w);
            }
        }
        __syncthreads();

        // ---- S = (Q * 1/8 via K scale) @ K^T : 16x64 per warp ----
        float s[8][4];
#pragma unroll
        for (int i = 0; i < 8; i++)
#pragma unroll
            for (int j = 0; j < 4; j++) s[i][j] = 0.f;
#pragma unroll
        for (int ksi = 0; ksi < 8; ksi++) {
#pragma unroll
            for (int nf = 0; nf < 8; nf++) {
                uint32_t b0 = __float_as_uint(ksm[(nf * 8 + g) * 68 + ksi * 8 + t]);
                uint32_t b1 = __float_as_uint(ksm[(nf * 8 + g) * 68 + ksi * 8 + t + 4]);
                mma_tf32(s[nf], qa[ksi][0], qa[ksi][1], qa[ksi][2], qa[ksi][3], b0, b1);
            }
        }

        // ---- online softmax (rows g via c0/c1, rows g+8 via c2/c3) ----
        float mx0 = -1e30f, mx1 = -1e30f;
#pragma unroll
        for (int nf = 0; nf < 8; nf++) {
            mx0 = fmaxf(mx0, fmaxf(s[nf][0], s[nf][1]));
            mx1 = fmaxf(mx1, fmaxf(s[nf][2], s[nf][3]));
        }
        mx0 = fmaxf(mx0, __shfl_xor_sync(0xffffffffu, mx0, 1));
        mx0 = fmaxf(mx0, __shfl_xor_sync(0xffffffffu, mx0, 2));
        mx1 = fmaxf(mx1, __shfl_xor_sync(0xffffffffu, mx1, 1));
        mx1 = fmaxf(mx1, __shfl_xor_sync(0xffffffffu, mx1, 2));
        float mn0 = fmaxf(m0, mx0), mn1 = fmaxf(m1, mx1);
        float al0 = __expf(m0 - mn0), al1 = __expf(m1 - mn1);
        float rs0 = 0.f, rs1 = 0.f;
#pragma unroll
        for (int nf = 0; nf < 8; nf++) {
            s[nf][0] = __expf(s[nf][0] - mn0);
            s[nf][1] = __expf(s[nf][1] - mn0);
            s[nf][2] = __expf(s[nf][2] - mn1);
            s[nf][3] = __expf(s[nf][3] - mn1);
            rs0 += s[nf][0] + s[nf][1];
            rs1 += s[nf][2] + s[nf][3];
        }
        rs0 += __shfl_xor_sync(0xffffffffu, rs0, 1);
        rs0 += __shfl_xor_sync(0xffffffffu, rs0, 2);
        rs1 += __shfl_xor_sync(0xffffffffu, rs1, 1);
        rs1 += __shfl_xor_sync(0xffffffffu, rs1, 2);
        l0 = l0 * al0 + rs0;
        l1 = l1 * al1 + rs1;
        m0 = mn0;
        m1 = mn1;
#pragma unroll
        for (int nf = 0; nf < 8; nf++) {
            o[nf][0] *= al0; o[nf][1] *= al0;
            o[nf][2] *= al1; o[nf][3] *= al1;
        }

        __syncthreads();   // all warps finished reading ksm (K) for S
        // ---- write P (tf32) into ksm; each warp owns its 16 rows ----
#pragma unroll
        for (int nf = 0; nf < 8; nf++) {
            int c = nf * 8 + 2 * t;
            *reinterpret_cast<float2*>(&ksm[pr0 + c]) =
                make_float2(f2tf(s[nf][0]), f2tf(s[nf][1]));
            *reinterpret_cast<float2*>(&ksm[pr1 + c]) =
                make_float2(f2tf(s[nf][2]), f2tf(s[nf][3]));
        }
        __syncwarp();      // warp reads only its own P rows below

        // ---- O += P @ V : 16x64 per warp, k = 64 (m dim) ----
#pragma unroll
        for (int k2 = 0; k2 < 8; k2++) {
            uint32_t pa0 = __float_as_uint(ksm[pr0 + k2 * 8 + t]);
            uint32_t pa1 = __float_as_uint(ksm[pr1 + k2 * 8 + t]);
            uint32_t pa2 = __float_as_uint(ksm[pr0 + k2 * 8 + t + 4]);
            uint32_t pa3 = __float_as_uint(ksm[pr1 + k2 * 8 + t + 4]);
#pragma unroll
            for (int nf = 0; nf < 8; nf++) {
                uint32_t b0 = __float_as_uint(vsm[(k2 * 8 + t)     * 72 + nf * 8 + g]);
                uint32_t b1 = __float_as_uint(vsm[(k2 * 8 + t + 4) * 72 + nf * 8 + g]);
                mma_tf32(o[nf], pa0, pa1, pa2, pa3, b0, b1);
            }
        }
    }

    // ---- epilogue: normalize + residual q, write out ----
    float il0 = 1.f / l0, il1 = 1.f / l1;
    const size_t r0o = qrow0 + g;
    const size_t r1o = qrow0 + g + 8;
#pragma unroll
    for (int nf = 0; nf < 8; nf++) {
        int c = nf * 8 + 2 * t;
        float2 q0 = *reinterpret_cast<const float2*>(g_Q + r0o * DD + c);
        float2 q1 = *reinterpret_cast<const float2*>(g_Q + r1o * DD + c);
        float2 v0 = make_float2(o[nf][0] * il0 + q0.x, o[nf][1] * il0 + q0.y);
        float2 v1 = make_float2(o[nf][2] * il1 + q1.x, o[nf][3] * il1 + q1.y);
        *reinterpret_cast<float2*>(out + r0o * DD + c) = v0;
        *reinterpret_cast<float2*>(out + r1o * DD + c) = v1;
    }
}

// ============================================================================
extern "C" void kernel_launch(void* const* d_in, const int* in_sizes, int n_in,
                              void* d_out, int out_size) {
    const float* x  = (const float*)d_in[0];
    const float* Wq = (const float*)d_in[1];
    const float* bq = (const float*)d_in[2];
    const float* Wk = (const float*)d_in[3];
    const float* bk = (const float*)d_in[4];
    const float* Wv = (const float*)d_in[5];
    const float* bv = (const float*)d_in[6];
    float* out = (float*)d_out;

    qkv_kernel<<<512, 256>>>(x, Wq, bq, Wk, bk, Wv, bv);
    attn_kernel<<<dim3(16, 64), 128>>>(out);
}

// round 10
// speedup vs baseline: 1.5973x; 1.5973x over previous
#include <cuda_runtime.h>
#include <cstdint>

// Problem constants
#define BB 64
#define NN 1024
#define CC 128
#define DD 64

// Scratch for Q, K, V (relu'd projections), fp32. __device__ globals (sanctioned scratch).
__device__ float g_Q[BB * NN * DD];
__device__ float g_K[BB * NN * DD];
__device__ float g_V[BB * NN * DD];

// Round fp32 -> tf32 (round-to-nearest) and return as a float bit-pattern.
__device__ __forceinline__ float f2tf(float f) {
    uint32_t u;
    asm("cvt.rna.tf32.f32 %0, %1;" : "=r"(u) : "f"(f));
    return __uint_as_float(u);
}

// m16n8k8 tf32 MMA, fp32 accumulate. A row-major, B col-major.
__device__ __forceinline__ void mma_tf32(float* d,
                                         uint32_t a0, uint32_t a1, uint32_t a2, uint32_t a3,
                                         uint32_t b0, uint32_t b1) {
    asm volatile(
        "mma.sync.aligned.m16n8k8.row.col.f32.tf32.tf32.f32 "
        "{%0,%1,%2,%3}, {%4,%5,%6,%7}, {%8,%9}, {%0,%1,%2,%3};"
        : "+f"(d[0]), "+f"(d[1]), "+f"(d[2]), "+f"(d[3])
        : "r"(a0), "r"(a1), "r"(a2), "r"(a3), "r"(b0), "r"(b1));
}

// ============================================================================
// Kernel 1: QKV projection.  dst = relu(x @ W + b), one matrix per blockIdx.x.
// Block: 128 threads = 4 warps. Tile: 128 rows x 64 cols. Warp = 32 rows.
// grid = (3, 512): matrix index fastest so x row-tiles stay L2-hot across Q/K/V.
// ============================================================================
__global__ __launch_bounds__(128) void qkv_kernel(
    const float* __restrict__ x,
    const float* __restrict__ Wq, const float* __restrict__ bq,
    const float* __restrict__ Wk, const float* __restrict__ bk,
    const float* __restrict__ Wv, const float* __restrict__ bv)
{
    __shared__ float xs[128 * 36];   // x chunk [128 rows][32 k], stride 36 (A-frag conflict-free)
    __shared__ float ws[32 * 72];    // W chunk [32 k][64 n],   stride 72 (B-frag conflict-free)

    const int tid  = threadIdx.x;
    const int w    = tid >> 5;
    const int lane = tid & 31;
    const int g    = lane >> 2;
    const int t    = lane & 3;
    const int mat  = blockIdx.x;          // 0:Q 1:K 2:V
    const int r0   = blockIdx.y * 128;

    const float* W    = (mat == 0) ? Wq : (mat == 1) ? Wk : Wv;
    const float* bias = (mat == 0) ? bq : (mat == 1) ? bk : bv;
    float* dst        = (mat == 0) ? g_Q : (mat == 1) ? g_K : g_V;

    float acc[2][8][4];
#pragma unroll
    for (int m = 0; m < 2; m++)
#pragma unroll
        for (int i = 0; i < 8; i++)
#pragma unroll
            for (int j = 0; j < 4; j++) acc[m][i][j] = 0.f;

    for (int kc = 0; kc < 4; kc++) {
        __syncthreads();
        // x chunk: 128x32 fp32 = 1024 float4, 8 per thread, tf32 into smem.
#pragma unroll
        for (int i = 0; i < 8; i++) {
            int v   = tid + i * 128;
            int row = v >> 3;
            int c4  = v & 7;
            float4 xv = *reinterpret_cast<const float4*>(
                x + (size_t)(r0 + row) * CC + kc * 32 + c4 * 4);
            *reinterpret_cast<float4*>(&xs[row * 36 + c4 * 4]) =
                make_float4(f2tf(xv.x), f2tf(xv.y), f2tf(xv.z), f2tf(xv.w));
        }
        // W chunk: 32x64 fp32 = 512 float4, 4 per thread.
#pragma unroll
        for (int i = 0; i < 4; i++) {
            int v   = tid + i * 128;
            int row = v >> 4;
            int c4  = v & 15;
            float4 wv = *reinterpret_cast<const float4*>(
                W + (size_t)(kc * 32 + row) * DD + c4 * 4);
            *reinterpret_cast<float4*>(&ws[row * 72 + c4 * 4]) =
                make_float4(f2tf(wv.x), f2tf(wv.y), f2tf(wv.z), f2tf(wv.w));
        }
        __syncthreads();

#pragma unroll
        for (int ksi = 0; ksi < 4; ksi++) {
            uint32_t a[2][4];
#pragma unroll
            for (int m = 0; m < 2; m++) {
                int ar = (w * 32 + m * 16 + g) * 36 + ksi * 8 + t;
                a[m][0] = __float_as_uint(xs[ar]);
                a[m][1] = __float_as_uint(xs[ar + 8 * 36]);
                a[m][2] = __float_as_uint(xs[ar + 4]);
                a[m][3] = __float_as_uint(xs[ar + 8 * 36 + 4]);
            }
#pragma unroll
            for (int nf = 0; nf < 8; nf++) {
                uint32_t b0 = __float_as_uint(ws[(ksi * 8 + t)     * 72 + nf * 8 + g]);
                uint32_t b1 = __float_as_uint(ws[(ksi * 8 + t + 4) * 72 + nf * 8 + g]);
                mma_tf32(acc[0][nf], a[0][0], a[0][1], a[0][2], a[0][3], b0, b1);
                mma_tf32(acc[1][nf], a[1][0], a[1][1], a[1][2], a[1][3], b0, b1);
            }
        }
    }

    // Epilogue: bias + relu.
#pragma unroll
    for (int m = 0; m < 2; m++) {
        const size_t rg = (size_t)r0 + w * 32 + m * 16 + g;
#pragma unroll
        for (int nf = 0; nf < 8; nf++) {
            int dcol = nf * 8 + 2 * t;
            float b0v = bias[dcol], b1v = bias[dcol + 1];
            *reinterpret_cast<float2*>(dst + rg * DD + dcol) =
                make_float2(fmaxf(acc[m][nf][0] + b0v, 0.f),
                            fmaxf(acc[m][nf][1] + b1v, 0.f));
            *reinterpret_cast<float2*>(dst + (rg + 8) * DD + dcol) =
                make_float2(fmaxf(acc[m][nf][2] + b0v, 0.f),
                            fmaxf(acc[m][nf][3] + b1v, 0.f));
        }
    }
}

// ============================================================================
// Kernel 2: flash attention + residual.  out = softmax(Q Kt / 8) @ V + Q
// CTA = 128 q-rows (grid 8 x 64), 4 warps, warp owns 32 rows (2 m-frags).
// Key-permutation trick: S-phase B fragments are loaded with key row
// pk(g) = (g>>1)|((g&1)<<2), so the S accumulator layout coincides with the
// PV A-fragment layout -> P never goes through smem.
// ============================================================================
__global__ __launch_bounds__(128) void attn_kernel(float* __restrict__ out)
{
    __shared__ float ksm[64 * 68];   // K tile (tf32, pre-scaled 1/8)
    __shared__ float vsm[64 * 72];   // V tile (tf32)

    const int tid  = threadIdx.x;
    const int w    = tid >> 5;
    const int lane = tid & 31;
    const int g    = lane >> 2;
    const int t    = lane & 3;
    const int b    = blockIdx.y;
    const int qt   = blockIdx.x;
    const int pkg  = (g >> 1) | ((g & 1) << 2);   // key permutation within 8-group
    const size_t qbase = (size_t)b * NN + qt * 128 + w * 32;

    // Q fragments in registers: 2 m-frags x 8 k-steps, tf32.
    uint32_t qa[2][8][4];
#pragma unroll
    for (int m = 0; m < 2; m++) {
        const float* qb = g_Q + (qbase + m * 16) * DD;
#pragma unroll
        for (int ksi = 0; ksi < 8; ksi++) {
            qa[m][ksi][0] = __float_as_uint(f2tf(qb[(size_t)g * DD + ksi * 8 + t]));
            qa[m][ksi][1] = __float_as_uint(f2tf(qb[(size_t)(g + 8) * DD + ksi * 8 + t]));
            qa[m][ksi][2] = __float_as_uint(f2tf(qb[(size_t)g * DD + ksi * 8 + t + 4]));
            qa[m][ksi][3] = __float_as_uint(f2tf(qb[(size_t)(g + 8) * DD + ksi * 8 + t + 4]));
        }
    }

    float o[2][8][4];
#pragma unroll
    for (int m = 0; m < 2; m++)
#pragma unroll
        for (int i = 0; i < 8; i++)
#pragma unroll
            for (int j = 0; j < 4; j++) o[m][i][j] = 0.f;
    float mrun[2][2] = {{-1e30f, -1e30f}, {-1e30f, -1e30f}};   // [m][row-half]
    float lrun[2][2] = {{0.f, 0.f}, {0.f, 0.f}};

    for (int kt = 0; kt < 16; kt++) {
        __syncthreads();   // previous iter's S/PV reads of ksm/vsm complete
        {
            const size_t base = ((size_t)b * NN + kt * 64) * DD;
#pragma unroll
            for (int i = 0; i < 8; i++) {
                int v   = tid + i * 128;
                int row = v >> 4;
                int c4  = v & 15;
                float4 kv = *reinterpret_cast<const float4*>(g_K + base + row * DD + c4 * 4);
                float4 vv = *reinterpret_cast<const float4*>(g_V + base + row * DD + c4 * 4);
                *reinterpret_cast<float4*>(&ksm[row * 68 + c4 * 4]) =
                    make_float4(f2tf(kv.x * 0.125f), f2tf(kv.y * 0.125f),
                                f2tf(kv.z * 0.125f), f2tf(kv.w * 0.125f));
                *reinterpret_cast<float4*>(&vsm[row * 72 + c4 * 4]) =
                    make_float4(f2tf(vv.x), f2tf(vv.y), f2tf(vv.z), f2tf(vv.w));
            }
        }
        __syncthreads();

        // ---- S = Q @ (K/8)^T : 32x64 per warp, keys permuted per 8-group ----
        float s[2][8][4];
#pragma unroll
        for (int m = 0; m < 2; m++)
#pragma unroll
            for (int i = 0; i < 8; i++)
#pragma unroll
                for (int j = 0; j < 4; j++) s[m][i][j] = 0.f;
#pragma unroll
        for (int ksi = 0; ksi < 8; ksi++) {
#pragma unroll
            for (int nf = 0; nf < 8; nf++) {
                int kr = (nf * 8 + pkg) * 68 + ksi * 8 + t;
                uint32_t b0 = __float_as_uint(ksm[kr]);
                uint32_t b1 = __float_as_uint(ksm[kr + 4]);
                mma_tf32(s[0][nf], qa[0][ksi][0], qa[0][ksi][1], qa[0][ksi][2], qa[0][ksi][3], b0, b1);
                mma_tf32(s[1][nf], qa[1][ksi][0], qa[1][ksi][1], qa[1][ksi][2], qa[1][ksi][3], b0, b1);
            }
        }

        // ---- online softmax per m-frag; exp'd P stays in s (tf32, in place) ----
#pragma unroll
        for (int m = 0; m < 2; m++) {
            float mx0 = -1e30f, mx1 = -1e30f;
#pragma unroll
            for (int nf = 0; nf < 8; nf++) {
                mx0 = fmaxf(mx0, fmaxf(s[m][nf][0], s[m][nf][1]));
                mx1 = fmaxf(mx1, fmaxf(s[m][nf][2], s[m][nf][3]));
            }
            mx0 = fmaxf(mx0, __shfl_xor_sync(0xffffffffu, mx0, 1));
            mx0 = fmaxf(mx0, __shfl_xor_sync(0xffffffffu, mx0, 2));
            mx1 = fmaxf(mx1, __shfl_xor_sync(0xffffffffu, mx1, 1));
            mx1 = fmaxf(mx1, __shfl_xor_sync(0xffffffffu, mx1, 2));
            float mn0 = fmaxf(mrun[m][0], mx0), mn1 = fmaxf(mrun[m][1], mx1);
            float al0 = __expf(mrun[m][0] - mn0), al1 = __expf(mrun[m][1] - mn1);
            float rs0 = 0.f, rs1 = 0.f;
#pragma unroll
            for (int nf = 0; nf < 8; nf++) {
                s[m][nf][0] = f2tf(__expf(s[m][nf][0] - mn0));
                s[m][nf][1] = f2tf(__expf(s[m][nf][1] - mn0));
                s[m][nf][2] = f2tf(__expf(s[m][nf][2] - mn1));
                s[m][nf][3] = f2tf(__expf(s[m][nf][3] - mn1));
                rs0 += s[m][nf][0] + s[m][nf][1];
                rs1 += s[m][nf][2] + s[m][nf][3];
            }
            rs0 += __shfl_xor_sync(0xffffffffu, rs0, 1);
            rs0 += __shfl_xor_sync(0xffffffffu, rs0, 2);
            rs1 += __shfl_xor_sync(0xffffffffu, rs1, 1);
            rs1 += __shfl_xor_sync(0xffffffffu, rs1, 2);
            lrun[m][0] = lrun[m][0] * al0 + rs0;
            lrun[m][1] = lrun[m][1] * al1 + rs1;
            mrun[m][0] = mn0;
            mrun[m][1] = mn1;
#pragma unroll
            for (int nf = 0; nf < 8; nf++) {
                o[m][nf][0] *= al0; o[m][nf][1] *= al0;
                o[m][nf][2] *= al1; o[m][nf][3] *= al1;
            }
        }

        // ---- O += P @ V : P comes straight from s (permutation-aligned) ----
#pragma unroll
        for (int k2 = 0; k2 < 8; k2++) {
#pragma unroll
            for (int nf = 0; nf < 8; nf++) {
                uint32_t b0 = __float_as_uint(vsm[(k2 * 8 + t)     * 72 + nf * 8 + g]);
                uint32_t b1 = __float_as_uint(vsm[(k2 * 8 + t + 4) * 72 + nf * 8 + g]);
                mma_tf32(o[0][nf],
                         __float_as_uint(s[0][k2][0]), __float_as_uint(s[0][k2][2]),
                         __float_as_uint(s[0][k2][1]), __float_as_uint(s[0][k2][3]), b0, b1);
                mma_tf32(o[1][nf],
                         __float_as_uint(s[1][k2][0]), __float_as_uint(s[1][k2][2]),
                         __float_as_uint(s[1][k2][1]), __float_as_uint(s[1][k2][3]), b0, b1);
            }
        }
    }

    // ---- epilogue: normalize + residual q ----
#pragma unroll
    for (int m = 0; m < 2; m++) {
        float il0 = 1.f / lrun[m][0], il1 = 1.f / lrun[m][1];
        const size_t r0o = qbase + m * 16 + g;
        const size_t r1o = r0o + 8;
#pragma unroll
        for (int nf = 0; nf < 8; nf++) {
            int c = nf * 8 + 2 * t;
            float2 q0 = *reinterpret_cast<const float2*>(g_Q + r0o * DD + c);
            float2 q1 = *reinterpret_cast<const float2*>(g_Q + r1o * DD + c);
            *reinterpret_cast<float2*>(out + r0o * DD + c) =
                make_float2(o[m][nf][0] * il0 + q0.x, o[m][nf][1] * il0 + q0.y);
            *reinterpret_cast<float2*>(out + r1o * DD + c) =
                make_float2(o[m][nf][2] * il1 + q1.x, o[m][nf][3] * il1 + q1.y);
        }
    }
}

// ============================================================================
extern "C" void kernel_launch(void* const* d_in, const int* in_sizes, int n_in,
                              void* d_out, int out_size) {
    const float* x  = (const float*)d_in[0];
    const float* Wq = (const float*)d_in[1];
    const float* bq = (const float*)d_in[2];
    const float* Wk = (const float*)d_in[3];
    const float* bk = (const float*)d_in[4];
    const float* Wv = (const float*)d_in[5];
    const float* bv = (const float*)d_in[6];
    float* out = (float*)d_out;

    qkv_kernel<<<dim3(3, 512), 128>>>(x, Wq, bq, Wk, bk, Wv, bv);
    attn_kernel<<<dim3(8, 64), 128>>>(out);
}